// round 11
// baseline (speedup 1.0000x reference)
#include <cuda_runtime.h>
#include <cuda_bf16.h>
#include <stdint.h>
#include <math.h>

#define NTHREADS 512
#define MAXCHUNKS 64
#define KC 32
#define BCHUNK 16384   // B bytes per split per chunk (32k x 256n x 2B)
#define ACHUNK 16384   // A raw bytes per chunk (128 x 32 f32)

// Prepped weights: [split hi/lo][chunk][k(32)][n(256)] bf16 (swizzle applied at cp.async dst)
__device__ __align__(16) unsigned char g_Bpre[2u * MAXCHUNKS * BCHUNK];  // 2 MB

// ---- dynamic smem layout (bytes) ----
#define BST    0                      // 3 stages x 32768 (hi 16KB + lo 16KB), swizzled
#define ARAW   98304                  // 3 stages x 16384 (A raw fp32 128x32)
#define ATIL   147456                 // 2 stages x 16384 (hi 8KB + lo 8KB), swizzled
#define SMEM_TOTAL 180224
// epilogue overlays (GEMM smem dead by then); acc dump occupies [0, 131072)
#define EP_P1   131072                // 4 x 128 floats
#define EP_P2   133120                // 4 x 128 floats
#define EP_COMP 135168
#define EP_CN   135680
#define EP_SSW  136192

static __device__ __forceinline__ uint32_t smem_u32(const void* p) {
    uint32_t a;
    asm("{ .reg .u64 t; cvta.to.shared.u64 t, %1; cvt.u32.u64 %0, t; }" : "=r"(a) : "l"(p));
    return a;
}
static __device__ __forceinline__ uint32_t cvt2(float hi, float lo) {
    uint32_t r;
    asm("cvt.rn.bf16x2.f32 %0, %1, %2;" : "=r"(r) : "f"(hi), "f"(lo));
    return r;
}
static __device__ __forceinline__ void cp16(uint32_t dst, const void* src) {
    asm volatile("cp.async.cg.shared.global [%0], [%1], 16;" :: "r"(dst), "l"(src));
}
#define CP_COMMIT() asm volatile("cp.async.commit_group;" ::: "memory")
#define CP_WAIT0()  asm volatile("cp.async.wait_group 0;" ::: "memory")
#define CP_WAIT1()  asm volatile("cp.async.wait_group 1;" ::: "memory")
#define CP_WAIT2()  asm volatile("cp.async.wait_group 2;" ::: "memory")

#define LDMX4(r, a) \
    asm volatile("ldmatrix.sync.aligned.m8n8.x4.shared.b16 {%0,%1,%2,%3}, [%4];" \
        : "=r"((r)[0]), "=r"((r)[1]), "=r"((r)[2]), "=r"((r)[3]) : "r"(a))
#define LDMX4T(r, a) \
    asm volatile("ldmatrix.sync.aligned.m8n8.x4.trans.shared.b16 {%0,%1,%2,%3}, [%4];" \
        : "=r"((r)[0]), "=r"((r)[1]), "=r"((r)[2]), "=r"((r)[3]) : "r"(a))
#define MMA16816(c, a, b0, b1) \
    asm volatile("mma.sync.aligned.m16n8k16.row.col.f32.bf16.bf16.f32 " \
        "{%0,%1,%2,%3},{%4,%5,%6,%7},{%8,%9},{%0,%1,%2,%3};" \
        : "+f"((c)[0]), "+f"((c)[1]), "+f"((c)[2]), "+f"((c)[3]) \
        : "r"((a)[0]), "r"((a)[1]), "r"((a)[2]), "r"((a)[3]), "r"(b0), "r"(b1))

// ---------------- prep: weights -> bf16 hi/lo split images, KC=32 chunks ----------------
__global__ void prep_b_kernel(const float* __restrict__ wkv, const float* __restrict__ wgate,
                              int nchunks) {
    int idx = blockIdx.x * blockDim.x + threadIdx.x;
    if (idx >= nchunks * 32 * 64) return;
    int n4 = idx & 63;           // group of 4 n-columns (n = n4*4, 0..255)
    int k  = (idx >> 6) & 31;    // k within chunk
    int c  = idx >> 11;          // chunk
    int kg = c * KC + k;
    int n  = n4 * 4;
    const float* w = (n < 128) ? (wkv + (size_t)kg * 128 + n)
                               : (wgate + (size_t)kg * 128 + (n - 128));
    float x0 = w[0], x1 = w[1], x2 = w[2], x3 = w[3];
    uint32_t h0 = cvt2(x1, x0), h1 = cvt2(x3, x2);
    float r0 = x0 - __uint_as_float(h0 << 16);
    float r1 = x1 - __uint_as_float(h0 & 0xFFFF0000u);
    float r2 = x2 - __uint_as_float(h1 << 16);
    float r3 = x3 - __uint_as_float(h1 & 0xFFFF0000u);
    uint32_t l0 = cvt2(r1, r0), l1 = cvt2(r3, r2);
    size_t off = (size_t)c * BCHUNK + (size_t)k * 512 + (size_t)n4 * 8;
    *(uint2*)(g_Bpre + off) = make_uint2(h0, h1);
    *(uint2*)(g_Bpre + (size_t)nchunks * BCHUNK + off) = make_uint2(l0, l1);
}

// ---------------- main fused kernel ----------------
__global__ void __launch_bounds__(NTHREADS, 1)
hca_mma_kernel(const float* __restrict__ hs,
               const int*   __restrict__ pos_ids,
               const float* __restrict__ bias,
               const float* __restrict__ norm_w,
               float*       __restrict__ out,
               int H, int nchunks)
{
    extern __shared__ __align__(16) unsigned char sm[];
    const uint32_t smb = smem_u32(sm);

    const int tid   = threadIdx.x;
    const int wid   = tid >> 5;
    const int lane  = tid & 31;
    const int mwarp = wid >> 2;   // 0..3 -> rows mwarp*32
    const int nwarp = wid & 3;    // 0..3 -> cols nwarp*64

    const float* hblk = hs + (size_t)blockIdx.x * 128 * (size_t)H;
    const size_t bLoOff = (size_t)nchunks * BCHUNK;

    // A raw chunk (128x32 f32 = 16KB): 1024 16B units, 2/thread, linear dst
    #define ISSUE_A(c_, s_) do { \
        const int k0_ = (c_) * KC; \
        _Pragma("unroll") \
        for (int i_ = 0; i_ < 2; ++i_) { \
            int u_ = tid + i_ * NTHREADS; \
            int row_ = u_ >> 3, jb_ = u_ & 7; \
            cp16(smb + ARAW + (s_) * ACHUNK + u_ * 16, \
                 hblk + (size_t)row_ * H + k0_ + jb_ * 4); \
        } \
    } while (0)
    // B chunk: per split 1024 16B units (32 rows x 512B), swizzle at dst
    #define ISSUE_B(c_, s_) do { \
        _Pragma("unroll") \
        for (int i_ = 0; i_ < 2; ++i_) { \
            int u_ = tid + i_ * NTHREADS; \
            int k_ = u_ >> 5, j_ = u_ & 31; \
            uint32_t doff_ = (uint32_t)k_ * 512 + (uint32_t)((j_ ^ (k_ & 7)) << 4); \
            const unsigned char* sH_ = g_Bpre + (size_t)(c_) * BCHUNK + (size_t)u_ * 16; \
            cp16(smb + BST + (s_) * 32768 + doff_, sH_); \
            cp16(smb + BST + (s_) * 32768 + 16384 + doff_, sH_ + bLoOff); \
        } \
    } while (0)
    // Split-convert half (i_) of next chunk's raw A into a tile stage.
    // A-tile swizzle (64B rows, 4x16B units): off = r*64 + ((jb16 ^ ((r>>1)&3))<<4) (+8 for odd half)
    #define CONV(i_, rs_, dst_) do { \
        int u_ = tid + (i_) * NTHREADS; \
        int row_ = u_ >> 3, jb_ = u_ & 7; \
        float4 x_ = *(const float4*)(sm + ARAW + (rs_) * ACHUNK + (size_t)u_ * 16); \
        uint32_t h0_ = cvt2(x_.y, x_.x), h1_ = cvt2(x_.w, x_.z); \
        float r0_ = x_.x - __uint_as_float(h0_ << 16); \
        float r1_ = x_.y - __uint_as_float(h0_ & 0xFFFF0000u); \
        float r2_ = x_.z - __uint_as_float(h1_ << 16); \
        float r3_ = x_.w - __uint_as_float(h1_ & 0xFFFF0000u); \
        uint32_t l0_ = cvt2(r1_, r0_), l1_ = cvt2(r3_, r2_); \
        uint32_t off_ = (uint32_t)row_ * 64 \
            + ((((uint32_t)(jb_ >> 1)) ^ (((uint32_t)row_ >> 1) & 3u)) << 4) \
            + (uint32_t)(jb_ & 1) * 8; \
        *(uint2*)((dst_) + off_) = make_uint2(h0_, h1_); \
        *(uint2*)((dst_) + 8192 + off_) = make_uint2(l0_, l1_); \
    } while (0)

    // prologue: 3-deep cp.async pipeline + convert chunk 0
    ISSUE_A(0, 0); ISSUE_B(0, 0); CP_COMMIT();
    if (nchunks > 1) { ISSUE_A(1, 1); ISSUE_B(1, 1); CP_COMMIT(); }
    if (nchunks > 2) { ISSUE_A(2, 2); ISSUE_B(2, 2); CP_COMMIT(); }
    CP_WAIT2();
    __syncthreads();
    {
        unsigned char* dst0 = sm + ATIL;
        CONV(0, 0, dst0);
        CONV(1, 0, dst0);
    }

    float acc[2][8][4];
    #pragma unroll
    for (int mi = 0; mi < 2; ++mi)
        #pragma unroll
        for (int ni = 0; ni < 8; ++ni)
            #pragma unroll
            for (int e = 0; e < 4; ++e) acc[mi][ni][e] = 0.f;

    // per-lane ldmatrix constants
    const uint32_t rBase = (uint32_t)(mwarp * 32) + (uint32_t)(lane & 15);
    const uint32_t keyM  = (rBase >> 1) & 3u;                    // A-tile XOR key
    const uint32_t aRowB = rBase * 64u;
    const uint32_t l4    = (uint32_t)(lane >> 4);
    const uint32_t bKlo  = (uint32_t)(lane & 15);                // k within k16 group
    const uint32_t keyB  = (uint32_t)(lane & 7);
    const uint32_t bNb   = (uint32_t)(nwarp * 8) + l4;           // 16B n-block base

    int s3 = 0;                       // c % 3
    int rs = (nchunks > 1) ? 1 : 0;   // (c+1) % 3

    #pragma unroll 1
    for (int c = 0; c < nchunks; ++c) {
        const int haveNext = (c + 1 < nchunks);
        if (c + 2 < nchunks)      CP_WAIT1();   // g_{c+1} done, g_{c+2} in flight
        else if (haveNext)        CP_WAIT0();   // tail: only g_{c+1} pending
        __syncthreads();

        const uint32_t bStage = smb + BST + (uint32_t)s3 * 32768u;
        const uint32_t atB    = smb + ATIL + (uint32_t)(c & 1) * 16384u;
        unsigned char* dstT   = sm + ATIL + ((c + 1) & 1) * 16384;

        #pragma unroll
        for (int kk = 0; kk < 2; ++kk) {
            uint32_t ah[2][4], al[2][4], bh[4][4], bl[4][4];
            const uint32_t aoff = (((uint32_t)(kk * 2) + l4) ^ keyM) << 4;
            const uint32_t bRow = (uint32_t)kk * 8192u + bKlo * 512u;
            #pragma unroll
            for (int mi = 0; mi < 2; ++mi)
                LDMX4(ah[mi], atB + aRowB + (uint32_t)mi * 1024u + aoff);
            #pragma unroll
            for (int ni2 = 0; ni2 < 4; ++ni2)
                LDMX4T(bh[ni2], bStage + bRow + (((bNb + (uint32_t)ni2 * 2u) ^ keyB) << 4));
            #pragma unroll
            for (int mi = 0; mi < 2; ++mi)
                #pragma unroll
                for (int ni2 = 0; ni2 < 4; ++ni2) {
                    MMA16816(acc[mi][ni2 * 2],     ah[mi], bh[ni2][0], bh[ni2][1]);
                    MMA16816(acc[mi][ni2 * 2 + 1], ah[mi], bh[ni2][2], bh[ni2][3]);
                }
            #pragma unroll
            for (int ni2 = 0; ni2 < 4; ++ni2)
                LDMX4T(bl[ni2], bStage + 16384u + bRow + (((bNb + (uint32_t)ni2 * 2u) ^ keyB) << 4));
            #pragma unroll
            for (int mi = 0; mi < 2; ++mi)
                #pragma unroll
                for (int ni2 = 0; ni2 < 4; ++ni2) {
                    MMA16816(acc[mi][ni2 * 2],     ah[mi], bl[ni2][0], bl[ni2][1]);
                    MMA16816(acc[mi][ni2 * 2 + 1], ah[mi], bl[ni2][2], bl[ni2][3]);
                }
            #pragma unroll
            for (int mi = 0; mi < 2; ++mi)
                LDMX4(al[mi], atB + 8192u + aRowB + (uint32_t)mi * 1024u + aoff);
            #pragma unroll
            for (int mi = 0; mi < 2; ++mi)
                #pragma unroll
                for (int ni2 = 0; ni2 < 4; ++ni2) {
                    MMA16816(acc[mi][ni2 * 2],     al[mi], bh[ni2][0], bh[ni2][1]);
                    MMA16816(acc[mi][ni2 * 2 + 1], al[mi], bh[ni2][2], bh[ni2][3]);
                }
            // interleave next-chunk A convert into the MMA stream
            if (haveNext) {
                if (kk == 0) CONV(0, rs, dstT);
                else         CONV(1, rs, dstT);
            }
        }
        __syncthreads();
        if (c + 3 < nchunks) { ISSUE_A(c + 3, s3); ISSUE_B(c + 3, s3); CP_COMMIT(); }
        s3 = rs;
        rs = (rs + 1 == 3) ? 0 : rs + 1;
    }

    // ---------------- epilogue (same math as round 7; 4-way partials) ----------------
    // Dump accums to bank-swizzled smem matrix at offset 0:
    //   val(r, col) @ r*1024 + (((col>>1) ^ (r&7)) << 3) + (col&1)*4
    #pragma unroll
    for (int mi = 0; mi < 2; ++mi) {
        int row0 = mwarp * 32 + mi * 16 + (lane >> 2);
        int row1 = row0 + 8;
        #pragma unroll
        for (int ni = 0; ni < 8; ++ni) {
            int pair = nwarp * 32 + ni * 4 + (lane & 3);
            *(float2*)(sm + row0 * 1024 + ((pair ^ (row0 & 7)) << 3)) =
                make_float2(acc[mi][ni][0], acc[mi][ni][1]);
            *(float2*)(sm + row1 * 1024 + ((pair ^ (row1 & 7)) << 3)) =
                make_float2(acc[mi][ni][2], acc[mi][ni][3]);
        }
    }
    __syncthreads();

    // softmax-weighted column reduction: S1 = sum_r exp(gate+bias), S2 = sum_r exp(..)*kv
    {
        const int d = tid & 127, q = tid >> 7;   // quarter 0..3, 32 rows each
        float s1 = 0.f, s2 = 0.f;
        #pragma unroll 8
        for (int ri = 0; ri < 32; ++ri) {
            int r = q * 32 + ri;
            float kv = *(const float*)(sm + r * 1024 + ((((d >> 1)      ) ^ (r & 7)) << 3) + (d & 1) * 4);
            float gv = *(const float*)(sm + r * 1024 + (((64 + (d >> 1)) ^ (r & 7)) << 3) + (d & 1) * 4);
            float g = gv + __ldg(&bias[r * 128 + d]);
            float e = expf(g);
            s1 += e;
            s2 += e * kv;
        }
        ((float*)(sm + EP_P1))[q * 128 + d] = s1;
        ((float*)(sm + EP_P2))[q * 128 + d] = s2;
    }
    __syncthreads();

    if (tid < 128) {
        float* P1 = (float*)(sm + EP_P1);
        float* P2 = (float*)(sm + EP_P2);
        float s1 = P1[tid] + P1[128 + tid] + P1[256 + tid] + P1[384 + tid];
        float s2 = P2[tid] + P2[128 + tid] + P2[256 + tid] + P2[384 + tid];
        float comp = s2 / s1;
        ((float*)(sm + EP_COMP))[tid] = comp;
        float ss = comp * comp;
        #pragma unroll
        for (int o = 16; o > 0; o >>= 1) ss += __shfl_xor_sync(0xffffffffu, ss, o);
        if (lane == 0) ((float*)(sm + EP_SSW))[wid] = ss;
    }
    __syncthreads();
    if (tid < 128) {
        float* SSW = (float*)(sm + EP_SSW);
        float tot = SSW[0] + SSW[1] + SSW[2] + SSW[3];
        float inv = rsqrtf(tot * (1.0f / 128.0f) + 1e-6f);
        ((float*)(sm + EP_CN))[tid] = ((float*)(sm + EP_COMP))[tid] * inv * __ldg(&norm_w[tid]);
    }
    __syncthreads();
    if (tid < 128) {
        const float* CN = (const float*)(sm + EP_CN);
        const int d = tid;
        float o;
        if (d < 64) {
            o = CN[d];
        } else {
            int jj = d - 64;
            int ii = jj >> 1;
            float posf = (float)__ldg(&pos_ids[(size_t)blockIdx.x * 128]);
            double pw  = pow(10000.0, (double)ii * (1.0 / 32.0));
            float invf = 1.0f / (float)pw;
            float freq = posf * invf;
            double a   = (double)freq;
            float cs = (float)cos(a);
            float sn = (float)sin(a);
            float r  = CN[d];
            float rh = (jj < 32) ? -CN[d + 32] : CN[d - 32];
            o = r * cs + rh * sn;
        }
        out[(size_t)blockIdx.x * 128 + d] = o;
    }
}

extern "C" void kernel_launch(void* const* d_in, const int* in_sizes, int n_in,
                              void* d_out, int out_size) {
    (void)n_in;
    const float* hs   = (const float*)d_in[0];   // hidden_states (B,S,H) f32
    const int*   pid  = (const int*)  d_in[2];   // position_ids (B,S) i32
    const float* wkv  = (const float*)d_in[3];   // (H,128)
    const float* wgt  = (const float*)d_in[4];   // (H,128)
    const float* bias = (const float*)d_in[5];   // (128,128)
    const float* nw   = (const float*)d_in[6];   // (128,)
    float* out = (float*)d_out;

    int H       = in_sizes[3] / 128;             // 2048
    int nchunks = H / KC;                        // 64
    int nblk    = out_size / 128;                // B*T = 128

    int prep_total = nchunks * 32 * 64;
    prep_b_kernel<<<(prep_total + 255) / 256, 256>>>(wkv, wgt, nchunks);

    cudaFuncSetAttribute(hca_mma_kernel, cudaFuncAttributeMaxDynamicSharedMemorySize, SMEM_TOTAL);
    hca_mma_kernel<<<nblk, NTHREADS, SMEM_TOTAL>>>(hs, pid, bias, nw, out, H, nchunks);
}

// round 13
// speedup vs baseline: 1.0986x; 1.0986x over previous
#include <cuda_runtime.h>
#include <cuda_bf16.h>
#include <stdint.h>
#include <math.h>

#define NTHREADS 256
#define MAXCHUNKS 32
#define KC 64
#define BCHUNK 32768   // B bytes per split per chunk (64k x 256n x 2B)
#define ACHUNK 32768   // A raw bytes per chunk (128 x 64 f32)

// Prepped weights: [split hi/lo][chunk][k(64)][n(256)] bf16 (swizzle applied at cp.async dst)
__device__ __align__(16) unsigned char g_Bpre[2u * MAXCHUNKS * BCHUNK];  // 2 MB

// ---- dynamic smem layout (bytes) ----
#define BST    0                      // 2 stages x 65536 (hi 32KB + lo 32KB), swizzled
#define ARAW   131072                 // 2 stages x 32768 (A raw fp32 128x64, swizzled for LDS)
#define SMEM_TOTAL 196608
// epilogue overlays (GEMM smem dead); acc dump occupies [0, 131072)
#define EP_P1   131072
#define EP_P2   132096
#define EP_COMP 133120
#define EP_CN   133632
#define EP_SSW  134144

static __device__ __forceinline__ uint32_t smem_u32(const void* p) {
    uint32_t a;
    asm("{ .reg .u64 t; cvta.to.shared.u64 t, %1; cvt.u32.u64 %0, t; }" : "=r"(a) : "l"(p));
    return a;
}
static __device__ __forceinline__ uint32_t cvt2(float hi, float lo) {
    uint32_t r;
    asm("cvt.rn.bf16x2.f32 %0, %1, %2;" : "=r"(r) : "f"(hi), "f"(lo));
    return r;
}
static __device__ __forceinline__ void cp16(uint32_t dst, const void* src) {
    asm volatile("cp.async.cg.shared.global [%0], [%1], 16;" :: "r"(dst), "l"(src));
}
#define CP_COMMIT() asm volatile("cp.async.commit_group;" ::: "memory")
#define CP_WAIT0()  asm volatile("cp.async.wait_group 0;" ::: "memory")
#define CP_WAIT1()  asm volatile("cp.async.wait_group 1;" ::: "memory")

static __device__ __forceinline__ float2 lds64(uint32_t a) {
    float2 v;
    asm volatile("ld.shared.v2.f32 {%0,%1}, [%2];" : "=f"(v.x), "=f"(v.y) : "r"(a));
    return v;
}
// split fp32 pair -> bf16x2 hi + bf16x2 lo (fragment-register layout: low half = first elem)
static __device__ __forceinline__ void splitpair(float2 p, uint32_t& h, uint32_t& l) {
    h = cvt2(p.y, p.x);
    float r0 = p.x - __uint_as_float(h << 16);
    float r1 = p.y - __uint_as_float(h & 0xFFFF0000u);
    l = cvt2(r1, r0);
}

#define LDMX4T(r, a) \
    asm volatile("ldmatrix.sync.aligned.m8n8.x4.trans.shared.b16 {%0,%1,%2,%3}, [%4];" \
        : "=r"((r)[0]), "=r"((r)[1]), "=r"((r)[2]), "=r"((r)[3]) : "r"(a))
#define MMA16816(c, a, b0, b1) \
    asm volatile("mma.sync.aligned.m16n8k16.row.col.f32.bf16.bf16.f32 " \
        "{%0,%1,%2,%3},{%4,%5,%6,%7},{%8,%9},{%0,%1,%2,%3};" \
        : "+f"((c)[0]), "+f"((c)[1]), "+f"((c)[2]), "+f"((c)[3]) \
        : "r"((a)[0]), "r"((a)[1]), "r"((a)[2]), "r"((a)[3]), "r"(b0), "r"(b1))

// ---------------- prep: weights -> bf16 hi/lo split images, KC=64 chunks ----------------
__global__ void prep_b_kernel(const float* __restrict__ wkv, const float* __restrict__ wgate,
                              int nchunks) {
    int idx = blockIdx.x * blockDim.x + threadIdx.x;
    if (idx >= nchunks * 64 * 64) return;
    int n4 = idx & 63;           // group of 4 n-columns (n = n4*4, 0..255)
    int k  = (idx >> 6) & 63;    // k within chunk
    int c  = idx >> 12;          // chunk
    int kg = c * KC + k;
    int n  = n4 * 4;
    const float* w = (n < 128) ? (wkv + (size_t)kg * 128 + n)
                               : (wgate + (size_t)kg * 128 + (n - 128));
    float x0 = w[0], x1 = w[1], x2 = w[2], x3 = w[3];
    uint32_t h0 = cvt2(x1, x0), h1 = cvt2(x3, x2);
    float r0 = x0 - __uint_as_float(h0 << 16);
    float r1 = x1 - __uint_as_float(h0 & 0xFFFF0000u);
    float r2 = x2 - __uint_as_float(h1 << 16);
    float r3 = x3 - __uint_as_float(h1 & 0xFFFF0000u);
    uint32_t l0 = cvt2(r1, r0), l1 = cvt2(r3, r2);
    size_t off = (size_t)c * BCHUNK + (size_t)k * 512 + (size_t)n4 * 8;
    *(uint2*)(g_Bpre + off) = make_uint2(h0, h1);
    *(uint2*)(g_Bpre + (size_t)nchunks * BCHUNK + off) = make_uint2(l0, l1);
}

// ---------------- main fused kernel ----------------
__global__ void __launch_bounds__(NTHREADS, 1)
hca_mma_kernel(const float* __restrict__ hs,
               const int*   __restrict__ pos_ids,
               const float* __restrict__ bias,
               const float* __restrict__ norm_w,
               float*       __restrict__ out,
               int H, int nchunks)
{
    extern __shared__ __align__(16) unsigned char sm[];
    const uint32_t smb = smem_u32(sm);

    const int tid   = threadIdx.x;
    const int wid   = tid >> 5;
    const int lane  = tid & 31;
    const int mwarp = wid >> 2;   // 0..1 -> rows mwarp*64
    const int nwarp = wid & 3;    // 0..3 -> cols nwarp*64

    const float* hblk = hs + (size_t)blockIdx.x * 128 * (size_t)H;
    const size_t bLoOff = (size_t)nchunks * BCHUNK;

    // One chunk = A raw (128x64 f32, 2048 16B units, LDS-swizzled) + B hi/lo (2048 units each)
    #define ISSUE(c_, s_) do { \
        const int k0_ = (c_) * KC; \
        _Pragma("unroll") \
        for (int i_ = 0; i_ < 8; ++i_) { \
            int u_ = tid + i_ * NTHREADS; \
            int row_ = u_ >> 4, v_ = u_ & 15; \
            uint32_t da_ = (uint32_t)row_ * 256u \
                + ((uint32_t)(v_ ^ (((row_ & 7) << 1))) << 4); \
            cp16(smb + ARAW + (s_) * ACHUNK + da_, \
                 hblk + (size_t)row_ * H + k0_ + v_ * 4); \
        } \
        _Pragma("unroll") \
        for (int i_ = 0; i_ < 8; ++i_) { \
            int u_ = tid + i_ * NTHREADS; \
            int k_ = u_ >> 5, j_ = u_ & 31; \
            uint32_t doff_ = (uint32_t)k_ * 512 + (uint32_t)((j_ ^ (k_ & 7)) << 4); \
            const unsigned char* sH_ = g_Bpre + (size_t)(c_) * BCHUNK + (size_t)u_ * 16; \
            cp16(smb + BST + (s_) * 65536 + doff_, sH_); \
            cp16(smb + BST + (s_) * 65536 + 32768 + doff_, sH_ + bLoOff); \
        } \
    } while (0)

    // prologue: 2-deep pipeline
    ISSUE(0, 0); CP_COMMIT();
    if (nchunks > 1) { ISSUE(1, 1); CP_COMMIT(); }

    float acc[4][8][4];
    #pragma unroll
    for (int mi = 0; mi < 4; ++mi)
        #pragma unroll
        for (int ni = 0; ni < 8; ++ni)
            #pragma unroll
            for (int e = 0; e < 4; ++e) acc[mi][ni][e] = 0.f;

    // per-lane constants
    const uint32_t keyA = ((uint32_t)(lane >> 2)) << 2;          // A swizzle key ((r&7)<<2)
    const uint32_t l2   = (uint32_t)(lane >> 2);                 // row-in-8
    const uint32_t jlo  = (uint32_t)(lane & 3);                  // k-pair low bits
    const uint32_t bKlo = (uint32_t)(lane & 15);                 // B k row within k16 group
    const uint32_t keyB = (uint32_t)(lane & 7);
    const uint32_t bNb  = (uint32_t)(nwarp * 8) + (uint32_t)(lane >> 4);

    #pragma unroll 1
    for (int c = 0; c < nchunks; ++c) {
        const int s = c & 1;
        if (c + 1 < nchunks) CP_WAIT1(); else CP_WAIT0();
        __syncthreads();

        const uint32_t bStage = smb + BST + (uint32_t)s * 65536u;
        const uint32_t aBase  = smb + ARAW + (uint32_t)s * ACHUNK;

        #pragma unroll
        for (int kk = 0; kk < 4; ++kk) {
            uint32_t ah[4][4], al[4][4], bh[4][4], bl[4][4];
            const uint32_t bRow = (uint32_t)kk * 8192u + bKlo * 512u;
            const uint32_t j1 = (uint32_t)kk * 8u + jlo;
            const uint32_t o1 = ((j1 ^ keyA) << 3);
            const uint32_t o2 = (((j1 + 4u) ^ keyA) << 3);

            // B hi fragments
            #pragma unroll
            for (int ni2 = 0; ni2 < 4; ++ni2)
                LDMX4T(bh[ni2], bStage + bRow + (((bNb + (uint32_t)ni2 * 2u) ^ keyB) << 4));

            // A fragments: direct LDS + in-register split convert (hi & lo together)
            #pragma unroll
            for (int mi = 0; mi < 4; ++mi) {
                uint32_t rowA = aBase + ((uint32_t)(mwarp * 64 + mi * 16) + l2) * 256u;
                float2 p0 = lds64(rowA + o1);
                float2 p1 = lds64(rowA + 2048u + o1);   // +8 rows
                float2 p2 = lds64(rowA + o2);
                float2 p3 = lds64(rowA + 2048u + o2);
                splitpair(p0, ah[mi][0], al[mi][0]);
                splitpair(p1, ah[mi][1], al[mi][1]);
                splitpair(p2, ah[mi][2], al[mi][2]);
                splitpair(p3, ah[mi][3], al[mi][3]);
            }

            // Ah x Bh
            #pragma unroll
            for (int mi = 0; mi < 4; ++mi)
                #pragma unroll
                for (int ni2 = 0; ni2 < 4; ++ni2) {
                    MMA16816(acc[mi][ni2 * 2],     ah[mi], bh[ni2][0], bh[ni2][1]);
                    MMA16816(acc[mi][ni2 * 2 + 1], ah[mi], bh[ni2][2], bh[ni2][3]);
                }
            // B lo fragments
            #pragma unroll
            for (int ni2 = 0; ni2 < 4; ++ni2)
                LDMX4T(bl[ni2], bStage + 32768u + bRow + (((bNb + (uint32_t)ni2 * 2u) ^ keyB) << 4));
            // Al x Bh (al dies here)
            #pragma unroll
            for (int mi = 0; mi < 4; ++mi)
                #pragma unroll
                for (int ni2 = 0; ni2 < 4; ++ni2) {
                    MMA16816(acc[mi][ni2 * 2],     al[mi], bh[ni2][0], bh[ni2][1]);
                    MMA16816(acc[mi][ni2 * 2 + 1], al[mi], bh[ni2][2], bh[ni2][3]);
                }
            // Ah x Bl
            #pragma unroll
            for (int mi = 0; mi < 4; ++mi)
                #pragma unroll
                for (int ni2 = 0; ni2 < 4; ++ni2) {
                    MMA16816(acc[mi][ni2 * 2],     ah[mi], bl[ni2][0], bl[ni2][1]);
                    MMA16816(acc[mi][ni2 * 2 + 1], ah[mi], bl[ni2][2], bl[ni2][3]);
                }
        }
        __syncthreads();   // all reads of stage s done before refilling it
        if (c + 2 < nchunks) { ISSUE(c + 2, s); CP_COMMIT(); }
    }

    // ---------------- epilogue (identical math to round 10) ----------------
    // Dump accums to bank-swizzled smem matrix at offset 0:
    //   val(r, col) @ r*1024 + (((col>>1) ^ (r&7)) << 3) + (col&1)*4
    #pragma unroll
    for (int mi = 0; mi < 4; ++mi) {
        int row0 = mwarp * 64 + mi * 16 + (lane >> 2);
        int row1 = row0 + 8;
        #pragma unroll
        for (int ni = 0; ni < 8; ++ni) {
            int pair = nwarp * 32 + ni * 4 + (lane & 3);
            *(float2*)(sm + row0 * 1024 + ((pair ^ (row0 & 7)) << 3)) =
                make_float2(acc[mi][ni][0], acc[mi][ni][1]);
            *(float2*)(sm + row1 * 1024 + ((pair ^ (row1 & 7)) << 3)) =
                make_float2(acc[mi][ni][2], acc[mi][ni][3]);
        }
    }
    __syncthreads();

    // softmax-weighted column reduction: S1 = sum_r exp(gate+bias), S2 = sum_r exp(..)*kv
    {
        const int d = tid & 127, half = tid >> 7;
        float s1 = 0.f, s2 = 0.f;
        #pragma unroll 8
        for (int ri = 0; ri < 64; ++ri) {
            int r = half * 64 + ri;
            float kv = *(const float*)(sm + r * 1024 + ((((d >> 1)      ) ^ (r & 7)) << 3) + (d & 1) * 4);
            float gv = *(const float*)(sm + r * 1024 + (((64 + (d >> 1)) ^ (r & 7)) << 3) + (d & 1) * 4);
            float g = gv + __ldg(&bias[r * 128 + d]);
            float e = expf(g);
            s1 += e;
            s2 += e * kv;
        }
        ((float*)(sm + EP_P1))[half * 128 + d] = s1;
        ((float*)(sm + EP_P2))[half * 128 + d] = s2;
    }
    __syncthreads();

    if (tid < 128) {
        float* P1 = (float*)(sm + EP_P1);
        float* P2 = (float*)(sm + EP_P2);
        float s1 = P1[tid] + P1[128 + tid];
        float s2 = P2[tid] + P2[128 + tid];
        float comp = s2 / s1;
        ((float*)(sm + EP_COMP))[tid] = comp;
        float ss = comp * comp;
        #pragma unroll
        for (int o = 16; o > 0; o >>= 1) ss += __shfl_xor_sync(0xffffffffu, ss, o);
        if (lane == 0) ((float*)(sm + EP_SSW))[wid] = ss;
    }
    __syncthreads();
    if (tid < 128) {
        float* SSW = (float*)(sm + EP_SSW);
        float tot = SSW[0] + SSW[1] + SSW[2] + SSW[3];
        float inv = rsqrtf(tot * (1.0f / 128.0f) + 1e-6f);
        ((float*)(sm + EP_CN))[tid] = ((float*)(sm + EP_COMP))[tid] * inv * __ldg(&norm_w[tid]);
    }
    __syncthreads();
    if (tid < 128) {
        const float* CN = (const float*)(sm + EP_CN);
        const int d = tid;
        float o;
        if (d < 64) {
            o = CN[d];
        } else {
            int jj = d - 64;
            int ii = jj >> 1;
            float posf = (float)__ldg(&pos_ids[(size_t)blockIdx.x * 128]);
            double pw  = pow(10000.0, (double)ii * (1.0 / 32.0));
            float invf = 1.0f / (float)pw;
            float freq = posf * invf;
            double a   = (double)freq;
            float cs = (float)cos(a);
            float sn = (float)sin(a);
            float r  = CN[d];
            float rh = (jj < 32) ? -CN[d + 32] : CN[d - 32];
            o = r * cs + rh * sn;
        }
        out[(size_t)blockIdx.x * 128 + d] = o;
    }
}

extern "C" void kernel_launch(void* const* d_in, const int* in_sizes, int n_in,
                              void* d_out, int out_size) {
    (void)n_in;
    const float* hs   = (const float*)d_in[0];   // hidden_states (B,S,H) f32
    const int*   pid  = (const int*)  d_in[2];   // position_ids (B,S) i32
    const float* wkv  = (const float*)d_in[3];   // (H,128)
    const float* wgt  = (const float*)d_in[4];   // (H,128)
    const float* bias = (const float*)d_in[5];   // (128,128)
    const float* nw   = (const float*)d_in[6];   // (128,)
    float* out = (float*)d_out;

    int H       = in_sizes[3] / 128;             // 2048
    int nchunks = H / KC;                        // 32
    int nblk    = out_size / 128;                // B*T = 128

    int prep_total = nchunks * 64 * 64;
    prep_b_kernel<<<(prep_total + 255) / 256, 256>>>(wkv, wgt, nchunks);

    cudaFuncSetAttribute(hca_mma_kernel, cudaFuncAttributeMaxDynamicSharedMemorySize, SMEM_TOTAL);
    hca_mma_kernel<<<nblk, NTHREADS, SMEM_TOTAL>>>(hs, pid, bias, nw, out, H, nchunks);
}

// round 15
// speedup vs baseline: 1.1276x; 1.0264x over previous
#include <cuda_runtime.h>
#include <cuda_bf16.h>
#include <stdint.h>
#include <math.h>

#define NTH 128
#define MAXCH 64
#define KC 32
#define BCHUNK 8192     // per (half,split,chunk): 32k x 128col x 2B
#define ACHUNK 16384    // A raw per chunk: 128 x 32 f32
#define STG 32768       // stage stride: A 16KB + B hi 8KB + B lo 8KB
#define SMEM_TOTAL 98304
// epilogue overlays (stages dead): acc dump [0,65536), partials at 65536+
#define EP_P1 65536
#define EP_P2 66048

// Prepped weights: [(half*2+split)][chunk][k(32)][col(128)] bf16, linear
__device__ __align__(16) unsigned char g_Bpre[4u * MAXCH * BCHUNK];  // 2 MB
// Per-block compressed vector (pre-RMS): [blk][128]
__device__ float g_comp[128 * 128];

static __device__ __forceinline__ uint32_t smem_u32(const void* p) {
    uint32_t a;
    asm("{ .reg .u64 t; cvta.to.shared.u64 t, %1; cvt.u32.u64 %0, t; }" : "=r"(a) : "l"(p));
    return a;
}
static __device__ __forceinline__ uint32_t cvt2(float hi, float lo) {
    uint32_t r;
    asm("cvt.rn.bf16x2.f32 %0, %1, %2;" : "=r"(r) : "f"(hi), "f"(lo));
    return r;
}
static __device__ __forceinline__ void cp16(uint32_t dst, const void* src) {
    asm volatile("cp.async.cg.shared.global [%0], [%1], 16;" :: "r"(dst), "l"(src));
}
#define CP_COMMIT() asm volatile("cp.async.commit_group;" ::: "memory")
#define CP_WAIT0()  asm volatile("cp.async.wait_group 0;" ::: "memory")
#define CP_WAIT1()  asm volatile("cp.async.wait_group 1;" ::: "memory")
#define CP_WAIT2()  asm volatile("cp.async.wait_group 2;" ::: "memory")

static __device__ __forceinline__ float2 lds64(uint32_t a) {
    float2 v;
    asm volatile("ld.shared.v2.f32 {%0,%1}, [%2];" : "=f"(v.x), "=f"(v.y) : "r"(a));
    return v;
}
static __device__ __forceinline__ void splitpair(float2 p, uint32_t& h, uint32_t& l) {
    h = cvt2(p.y, p.x);
    float r0 = p.x - __uint_as_float(h << 16);
    float r1 = p.y - __uint_as_float(h & 0xFFFF0000u);
    l = cvt2(r1, r0);
}

#define LDMX4T(r, a) \
    asm volatile("ldmatrix.sync.aligned.m8n8.x4.trans.shared.b16 {%0,%1,%2,%3}, [%4];" \
        : "=r"((r)[0]), "=r"((r)[1]), "=r"((r)[2]), "=r"((r)[3]) : "r"(a))
#define MMA16816(c, a, b0, b1) \
    asm volatile("mma.sync.aligned.m16n8k16.row.col.f32.bf16.bf16.f32 " \
        "{%0,%1,%2,%3},{%4,%5,%6,%7},{%8,%9},{%0,%1,%2,%3};" \
        : "+f"((c)[0]), "+f"((c)[1]), "+f"((c)[2]), "+f"((c)[3]) \
        : "r"((a)[0]), "r"((a)[1]), "r"((a)[2]), "r"((a)[3]), "r"(b0), "r"(b1))

// ---------------- prep: weights -> per-half bf16 hi/lo images ----------------
// local col j<64 -> w_kv[:, h*64+j] ; j>=64 -> w_gate[:, h*64+(j-64)]
__global__ void prep_b_kernel(const float* __restrict__ wkv, const float* __restrict__ wgate,
                              int nch) {
    int idx = blockIdx.x * blockDim.x + threadIdx.x;
    int per = nch << 10;                  // nch * 1024 (32k x 32 col-groups)
    if (idx >= 2 * per) return;
    int h   = idx / per;
    int rem = idx - h * per;
    int c   = rem >> 10;
    int w10 = rem & 1023;
    int k   = w10 >> 5;
    int g   = w10 & 31;
    int j0  = g * 4;
    int kg  = c * KC + k;
    const float* src = (j0 < 64) ? (wkv   + (size_t)kg * 128 + h * 64 + j0)
                                 : (wgate + (size_t)kg * 128 + h * 64 + (j0 - 64));
    float x0 = src[0], x1 = src[1], x2 = src[2], x3 = src[3];
    uint32_t h0 = cvt2(x1, x0), h1 = cvt2(x3, x2);
    float r0 = x0 - __uint_as_float(h0 << 16);
    float r1 = x1 - __uint_as_float(h0 & 0xFFFF0000u);
    float r2 = x2 - __uint_as_float(h1 << 16);
    float r3 = x3 - __uint_as_float(h1 & 0xFFFF0000u);
    uint32_t l0 = cvt2(r1, r0), l1 = cvt2(r3, r2);
    size_t off = (size_t)k * 256 + (size_t)j0 * 2;
    *(uint2*)(g_Bpre + ((size_t)(h * 2 + 0) * nch + c) * BCHUNK + off) = make_uint2(h0, h1);
    *(uint2*)(g_Bpre + ((size_t)(h * 2 + 1) * nch + c) * BCHUNK + off) = make_uint2(l0, l1);
}

// ---------------- GEMM + softmax-reduce kernel (2 CTAs per token-block) ----------------
__global__ void __launch_bounds__(NTH)
hca_gemm_kernel(const float* __restrict__ hs,
                const float* __restrict__ bias,
                int H, int nch)
{
    extern __shared__ __align__(16) unsigned char sm[];
    const uint32_t smb = smem_u32(sm);

    const int tid   = threadIdx.x;
    const int wid   = tid >> 5;     // 0..3
    const int lane  = tid & 31;
    const int mwarp = wid >> 1;     // 0..1 -> rows mwarp*64
    const int nwarp = wid & 1;      // 0..1 -> local cols nwarp*64

    const int blk  = blockIdx.x >> 1;
    const int half = blockIdx.x & 1;

    const float* hblk = hs + (size_t)blk * 128 * (size_t)H;

    // one chunk: A (1024 16B units) + B hi/lo (512 units each)
    #define ISSUE(c_, st_) do { \
        const int k0_ = (c_) * KC; \
        _Pragma("unroll") \
        for (int i_ = 0; i_ < 8; ++i_) { \
            int u_ = tid + i_ * NTH; \
            int row_ = u_ >> 3, v_ = u_ & 7; \
            uint32_t da_ = (uint32_t)row_ * 128u + ((uint32_t)(v_ ^ (row_ & 7)) << 4); \
            cp16(smb + (st_) * STG + da_, hblk + (size_t)row_ * H + k0_ + v_ * 4); \
        } \
        _Pragma("unroll") \
        for (int i_ = 0; i_ < 8; ++i_) { \
            int u_ = tid + i_ * NTH; \
            int sp_ = u_ >> 9, w_ = u_ & 511; \
            int k_ = w_ >> 4, j_ = w_ & 15; \
            uint32_t db_ = (uint32_t)(16384 + sp_ * 8192) + (uint32_t)k_ * 256u \
                + ((uint32_t)(j_ ^ (k_ & 7)) << 4); \
            cp16(smb + (st_) * STG + db_, \
                 g_Bpre + ((size_t)(half * 2 + sp_) * nch + (c_)) * BCHUNK + (size_t)w_ * 16); \
        } \
    } while (0)

    ISSUE(0, 0); CP_COMMIT();
    if (nch > 1) { ISSUE(1, 1); CP_COMMIT(); }
    if (nch > 2) { ISSUE(2, 2); CP_COMMIT(); }

    float acc[4][8][4];
    #pragma unroll
    for (int mi = 0; mi < 4; ++mi)
        #pragma unroll
        for (int ni = 0; ni < 8; ++ni)
            #pragma unroll
            for (int e = 0; e < 4; ++e) acc[mi][ni][e] = 0.f;

    // per-lane constants
    const uint32_t keyA = (uint32_t)(lane >> 2);   // = row&7 for all fragment rows
    const uint32_t p    = (uint32_t)(lane & 3);
    const uint32_t keyB = (uint32_t)(lane & 7);    // = (B k-row)&7
    const uint32_t bKlo = (uint32_t)(lane & 15);
    const uint32_t bNb  = (uint32_t)(nwarp * 8) + (uint32_t)(lane >> 4);

    int st = 0;
    #pragma unroll 1
    for (int c = 0; c < nch; ++c) {
        if (c + 2 < nch)      CP_WAIT2();
        else if (c + 1 < nch) CP_WAIT1();
        else                  CP_WAIT0();
        __syncthreads();

        const uint32_t aBase = smb + (uint32_t)st * STG;
        const uint32_t bBase = aBase + 16384u;

        #pragma unroll
        for (int kk = 0; kk < 2; ++kk) {
            uint32_t ah[4][4], al[4][4], bh[4][4], bl[4][4];
            const uint32_t u1 = (uint32_t)(kk * 4) + (p >> 1);
            const uint32_t o1 = ((u1 ^ keyA) << 4) + (p & 1) * 8u;
            const uint32_t o2 = (((u1 + 2u) ^ keyA) << 4) + (p & 1) * 8u;
            const uint32_t bRow = (uint32_t)kk * 4096u + bKlo * 256u;

            // B hi fragments (4 x n16)
            #pragma unroll
            for (int ni2 = 0; ni2 < 4; ++ni2)
                LDMX4T(bh[ni2], bBase + bRow + (((bNb + (uint32_t)ni2 * 2u) ^ keyB) << 4));

            // A fragments: direct LDS + split convert
            #pragma unroll
            for (int mi = 0; mi < 4; ++mi) {
                uint32_t rowA = aBase + ((uint32_t)(mwarp * 64 + mi * 16) + (uint32_t)(lane >> 2)) * 128u;
                float2 p0 = lds64(rowA + o1);
                float2 p1 = lds64(rowA + 1024u + o1);   // +8 rows
                float2 p2 = lds64(rowA + o2);
                float2 p3 = lds64(rowA + 1024u + o2);
                splitpair(p0, ah[mi][0], al[mi][0]);
                splitpair(p1, ah[mi][1], al[mi][1]);
                splitpair(p2, ah[mi][2], al[mi][2]);
                splitpair(p3, ah[mi][3], al[mi][3]);
            }

            // Ah x Bh
            #pragma unroll
            for (int mi = 0; mi < 4; ++mi)
                #pragma unroll
                for (int ni2 = 0; ni2 < 4; ++ni2) {
                    MMA16816(acc[mi][ni2 * 2],     ah[mi], bh[ni2][0], bh[ni2][1]);
                    MMA16816(acc[mi][ni2 * 2 + 1], ah[mi], bh[ni2][2], bh[ni2][3]);
                }
            // B lo fragments
            #pragma unroll
            for (int ni2 = 0; ni2 < 4; ++ni2)
                LDMX4T(bl[ni2], bBase + 8192u + bRow + (((bNb + (uint32_t)ni2 * 2u) ^ keyB) << 4));
            // Al x Bh
            #pragma unroll
            for (int mi = 0; mi < 4; ++mi)
                #pragma unroll
                for (int ni2 = 0; ni2 < 4; ++ni2) {
                    MMA16816(acc[mi][ni2 * 2],     al[mi], bh[ni2][0], bh[ni2][1]);
                    MMA16816(acc[mi][ni2 * 2 + 1], al[mi], bh[ni2][2], bh[ni2][3]);
                }
            // Ah x Bl
            #pragma unroll
            for (int mi = 0; mi < 4; ++mi)
                #pragma unroll
                for (int ni2 = 0; ni2 < 4; ++ni2) {
                    MMA16816(acc[mi][ni2 * 2],     ah[mi], bl[ni2][0], bl[ni2][1]);
                    MMA16816(acc[mi][ni2 * 2 + 1], ah[mi], bl[ni2][2], bl[ni2][3]);
                }
        }
        __syncthreads();
        if (c + 3 < nch) { ISSUE(c + 3, st); CP_COMMIT(); }
        st = (st + 1 == 3) ? 0 : st + 1;
    }

    // ---- dump accumulators to bank-swizzled smem (128 rows x 128 local cols) ----
    // val(r, j) @ r*512 + (((j>>1) ^ (r&7)) << 3) + (j&1)*4
    #pragma unroll
    for (int mi = 0; mi < 4; ++mi) {
        int row0 = mwarp * 64 + mi * 16 + (lane >> 2);
        int row1 = row0 + 8;
        #pragma unroll
        for (int ni = 0; ni < 8; ++ni) {
            int pair = nwarp * 32 + ni * 4 + (lane & 3);
            *(float2*)(sm + row0 * 512 + ((pair ^ (row0 & 7)) << 3)) =
                make_float2(acc[mi][ni][0], acc[mi][ni][1]);
            *(float2*)(sm + row1 * 512 + ((pair ^ (row1 & 7)) << 3)) =
                make_float2(acc[mi][ni][2], acc[mi][ni][3]);
        }
    }
    __syncthreads();

    // softmax-weighted reduction for this half's 64 dims:
    // local col d = kv, local col 64+d = gate
    {
        const int dloc = tid & 63, seg = tid >> 6;   // 2 segs x 64 rows
        float s1 = 0.f, s2 = 0.f;
        #pragma unroll 8
        for (int ri = 0; ri < 64; ++ri) {
            int r = seg * 64 + ri;
            float kv = *(const float*)(sm + r * 512 + ((((dloc >> 1)      ) ^ (r & 7)) << 3) + (dloc & 1) * 4);
            float gv = *(const float*)(sm + r * 512 + (((32 + (dloc >> 1)) ^ (r & 7)) << 3) + (dloc & 1) * 4);
            float g = gv + __ldg(&bias[r * 128 + half * 64 + dloc]);
            float e = expf(g);
            s1 += e;
            s2 += e * kv;
        }
        ((float*)(sm + EP_P1))[seg * 64 + dloc] = s1;
        ((float*)(sm + EP_P2))[seg * 64 + dloc] = s2;
    }
    __syncthreads();
    if (tid < 64) {
        float* P1 = (float*)(sm + EP_P1);
        float* P2 = (float*)(sm + EP_P2);
        float s1 = P1[tid] + P1[64 + tid];
        float s2 = P2[tid] + P2[64 + tid];
        g_comp[blk * 128 + half * 64 + tid] = s2 / s1;
    }
}

// ---------------- finish kernel: RMS norm + RoPE ----------------
__global__ void __launch_bounds__(128)
hca_finish_kernel(const int* __restrict__ pos_ids,
                  const float* __restrict__ norm_w,
                  float* __restrict__ out)
{
    __shared__ float cn[128];
    __shared__ float sw[4];
    const int b = blockIdx.x, tid = threadIdx.x;
    const int wid = tid >> 5, lane = tid & 31;

    float comp = g_comp[b * 128 + tid];
    float ss = comp * comp;
    #pragma unroll
    for (int o = 16; o > 0; o >>= 1) ss += __shfl_xor_sync(0xffffffffu, ss, o);
    if (lane == 0) sw[wid] = ss;
    __syncthreads();
    float tot = sw[0] + sw[1] + sw[2] + sw[3];
    float inv = rsqrtf(tot * (1.0f / 128.0f) + 1e-6f);
    cn[tid] = comp * inv * __ldg(&norm_w[tid]);
    __syncthreads();

    const int d = tid;
    float o;
    if (d < 64) {
        o = cn[d];
    } else {
        int jj = d - 64;
        int ii = jj >> 1;
        float posf = (float)__ldg(&pos_ids[(size_t)b * 128]);
        double pw  = pow(10000.0, (double)ii * (1.0 / 32.0));
        float invf = 1.0f / (float)pw;
        float freq = posf * invf;
        double a   = (double)freq;
        float cs = (float)cos(a);
        float sn = (float)sin(a);
        float r  = cn[d];
        float rh = (jj < 32) ? -cn[d + 32] : cn[d - 32];
        o = r * cs + rh * sn;
    }
    out[(size_t)b * 128 + d] = o;
}

extern "C" void kernel_launch(void* const* d_in, const int* in_sizes, int n_in,
                              void* d_out, int out_size) {
    (void)n_in;
    const float* hs   = (const float*)d_in[0];   // hidden_states (B,S,H) f32
    const int*   pid  = (const int*)  d_in[2];   // position_ids (B,S) i32
    const float* wkv  = (const float*)d_in[3];   // (H,128)
    const float* wgt  = (const float*)d_in[4];   // (H,128)
    const float* bias = (const float*)d_in[5];   // (128,128)
    const float* nw   = (const float*)d_in[6];   // (128,)
    float* out = (float*)d_out;

    int H    = in_sizes[3] / 128;                // 2048
    int nch  = H / KC;                           // 64
    int nblk = out_size / 128;                   // B*T = 128

    int prep_total = 2 * nch * 1024;
    prep_b_kernel<<<(prep_total + 255) / 256, 256>>>(wkv, wgt, nch);

    cudaFuncSetAttribute(hca_gemm_kernel, cudaFuncAttributeMaxDynamicSharedMemorySize, SMEM_TOTAL);
    hca_gemm_kernel<<<nblk * 2, NTH, SMEM_TOTAL>>>(hs, bias, H, nch);

    hca_finish_kernel<<<nblk, 128>>>(pid, nw, out);
}